// round 14
// baseline (speedup 1.0000x reference)
#include <cuda_runtime.h>

typedef unsigned long long u64;

#define J 5
#define L2E 1.4426950408889634f
#define LN2 0.6931471805599453f
#define E1F 2.7182818284590452f

#define TABN 2048
#define TABH 0.0078125f      // 1/128
#define TABIH 128.0f

// sigmoid(0.5+u) Taylor coefficients, u in [-0.6, 0.6], |err| < 3e-6
#define SC0 0.62245933f
#define SC1 0.23500371f
#define SC2 (-0.02877850f)
#define SC3 (-0.01605943f)
#define SC4 0.00436497f
#define SC5 0.00113020f
#define SC6 (-0.00054212f)

// F(s) table: {F, F', F'', F'''} at s = i/128
__device__ float4 d_tab[TABN];

// ---- scalar approx helpers ----
__device__ __forceinline__ float ex2f(float x){ float r; asm("ex2.approx.f32 %0,%1;":"=f"(r):"f"(x)); return r; }
__device__ __forceinline__ float rcpf(float x){ float r; asm("rcp.approx.f32 %0,%1;":"=f"(r):"f"(x)); return r; }
__device__ __forceinline__ float rsqf(float x){ float r; asm("rsqrt.approx.f32 %0,%1;":"=f"(r):"f"(x)); return r; }

// ---- packed f32x2 helpers (sm_103a) ----
__device__ __forceinline__ u64 fma2_(u64 a,u64 b,u64 c){u64 d;asm("fma.rn.f32x2 %0,%1,%2,%3;":"=l"(d):"l"(a),"l"(b),"l"(c));return d;}
__device__ __forceinline__ u64 mul2_(u64 a,u64 b){u64 d;asm("mul.rn.f32x2 %0,%1,%2;":"=l"(d):"l"(a),"l"(b));return d;}
__device__ __forceinline__ u64 add2_(u64 a,u64 b){u64 d;asm("add.rn.f32x2 %0,%1,%2;":"=l"(d):"l"(a),"l"(b));return d;}
__device__ __forceinline__ u64 pk2(float lo,float hi){u64 d;asm("mov.b64 %0,{%1,%2};":"=l"(d):"f"(lo),"f"(hi));return d;}
__device__ __forceinline__ void up2(u64 v,float&lo,float&hi){asm("mov.b64 {%0,%1},%2;":"=f"(lo),"=f"(hi):"l"(v));}
__device__ __forceinline__ u64 bc2(float x){ return pk2(x,x); }
__device__ __forceinline__ u64 ex2p(u64 x){float l,h;up2(x,l,h);return pk2(ex2f(l),ex2f(h));}
__device__ __forceinline__ u64 rcpp(u64 x){float l,h;up2(x,l,h);return pk2(rcpf(l),rcpf(h));}
__device__ __forceinline__ u64 rsqp(u64 x){float l,h;up2(x,l,h);return pk2(rsqf(l),rsqf(h));}
__device__ __forceinline__ u64 neg2(u64 x){ return x ^ 0x8000000080000000ULL; }  // alu pipe

// Build table of F(s) = Wo.softplus(W2.softplus(r1*s + c1) + b2) + bo and
// its first three derivatives wrt the scalar s. One node per thread.
__global__ void table_kernel(const float* __restrict__ bexp,
                             const float* __restrict__ W1, const float* __restrict__ b1,
                             const float* __restrict__ W2, const float* __restrict__ b2,
                             const float* __restrict__ Wo, const float* __restrict__ bo)
{
    cudaTriggerProgrammaticLaunchCompletion();

    int i = blockIdx.x * blockDim.x + threadIdx.x;
    if (i >= TABN) return;
    float s = (float)i * TABH;

    float h1[J], d1[J], dd1[J], ddd1[J];
    #pragma unroll
    for (int j = 0; j < J; ++j) {
        float r = 0.f, c = b1[j];
        #pragma unroll
        for (int k = 0; k < J; ++k) {
            float w = W1[j*J + k];
            r += w;
            c = fmaf(w, bexp[k], c);
        }
        float z   = fmaf(r, s, c);
        float e   = ex2f(-fabsf(z) * L2E);          // exp(-|z|)
        float inv = rcpf(1.f + e);
        float sg  = (z >= 0.f) ? inv : 1.f - inv;   // sigmoid(z)
        float sg1 = sg * (1.f - sg);
        float sg2 = sg1 * (1.f - 2.f * sg);
        h1[j]   = fmaxf(z, 0.f) + __logf(1.f + e);  // softplus(z)
        d1[j]   = sg * r;
        dd1[j]  = sg1 * r * r;
        ddd1[j] = sg2 * r * r * r;
    }

    float F = bo[0], F1 = 0.f, F2 = 0.f, F3 = 0.f;
    #pragma unroll
    for (int j = 0; j < J; ++j) {
        float z2 = b2[j], q = 0.f, m = 0.f, n3 = 0.f;
        #pragma unroll
        for (int k = 0; k < J; ++k) {
            float w = W2[j*J + k];
            z2 = fmaf(w, h1[k], z2);
            q  = fmaf(w, d1[k], q);
            m  = fmaf(w, dd1[k], m);
            n3 = fmaf(w, ddd1[k], n3);
        }
        float e   = ex2f(-fabsf(z2) * L2E);
        float inv = rcpf(1.f + e);
        float sg  = (z2 >= 0.f) ? inv : 1.f - inv;
        float sp  = fmaxf(z2, 0.f) + __logf(1.f + e);
        float sg1 = sg * (1.f - sg);
        float sg2 = sg1 * (1.f - 2.f * sg);
        float wo = Wo[j];
        F  = fmaf(wo, sp, F);
        F1 = fmaf(wo, sg * q, F1);
        F2 = fmaf(wo, fmaf(sg1, q * q, sg * m), F2);
        F3 = fmaf(wo, sg2 * q * q * q + 3.f * sg1 * q * m + sg * n3, F3);
    }
    d_tab[i] = make_float4(F, F1, F2, F3);
}

__global__ __launch_bounds__(256)
void smile_kernel(const float2* __restrict__ ttm2,
                  const float2* __restrict__ logm2,
                  float2* __restrict__ o0, float2* __restrict__ o1,
                  float2* __restrict__ o2, float2* __restrict__ o3,
                  const float* __restrict__ wlogm, const float* __restrict__ blogm,
                  const float* __restrict__ wttm,  const float* __restrict__ bttm,
                  const float* __restrict__ wexp,
                  int nvec)
{
    // Per-block broadcast-packed constants (all loads via LDS.128):
    // scb[j] = {wl*L2E, bl*L2E, wt, bt-0.5, we, we*wt, we*wl/2, we*wl^2/2}
    __shared__ __align__(16) u64 scb[J][8];
    // cc = broadcast arithmetic + sigmoid-poly constants
    __shared__ __align__(16) u64 cc[16];
    if (threadIdx.x < J) {
        int j = threadIdx.x;
        float wl = __expf(wlogm[j]);
        float wt = __expf(wttm[j]);
        float we = __expf(wexp[j]);
        scb[j][0] = bc2(wl * L2E);
        scb[j][1] = bc2(blogm[j] * L2E);
        scb[j][2] = bc2(wt);
        scb[j][3] = bc2(bttm[j] - 0.5f);        // center for sigmoid poly
        scb[j][4] = bc2(we);
        scb[j][5] = bc2(we * wt);
        scb[j][6] = bc2(we * wl * 0.5f);        // 1/2 of T' folded here
        scb[j][7] = bc2(we * wl * wl * 0.5f);   // 1/2 of T'' folded here
    }
    if (threadIdx.x == 32) {                    // separate warp: no divergence cost
        cc[0]  = bc2(1.f);      cc[1]  = bc2(-1.f);
        cc[2]  = bc2(2.f);      cc[3]  = bc2(-2.f);
        cc[4]  = bc2(0.5f);     cc[5]  = bc2(-0.5f);
        cc[6]  = bc2(5e-4f);    cc[7]  = bc2(E1F);
        cc[8]  = bc2(LN2);      cc[9]  = bc2(SC6);
        cc[10] = bc2(SC5);      cc[11] = bc2(SC4);
        cc[12] = bc2(SC3);      cc[13] = bc2(SC2);
        cc[14] = bc2(SC1);      cc[15] = bc2(SC0);
    }
    __syncthreads();

    int v = blockIdx.x * blockDim.x + threadIdx.x;
    if (v >= nvec) return;

    float2 t2i = ttm2[v];
    float2 l2i = logm2[v];
    u64 tt2 = pk2(t2i.x, t2i.y);
    u64 ll2 = pk2(l2i.x, l2i.y);

    // vectorized constant loads (8 LDS.128)
    const ulonglong2* ccv = reinterpret_cast<const ulonglong2*>(cc);
    ulonglong2 k0 = ccv[0], k1 = ccv[1], k2 = ccv[2], k3 = ccv[3];
    ulonglong2 k4 = ccv[4], k5 = ccv[5], k6 = ccv[6], k7 = ccv[7];
    u64 one2 = k0.x, cm1    = k0.y;
    u64 two2 = k1.x, m2c    = k1.y;
    u64 half2= k2.x, nhalf2 = k2.y;
    u64 c5e4 = k3.x, e2     = k3.y;
    u64 ln2_2= k4.x, C6     = k4.y;
    u64 C5   = k5.x, C4     = k5.y;
    u64 C3   = k6.x, C2     = k6.y;
    u64 C1   = k7.x, C0     = k7.y;

    u64 s2  = 0ull;
    u64 st2 = 0ull;
    u64 sl2 = 0ull;
    u64 sll2= 0ull;

    // ---- Part 1: packed smile/sigmoid terms + derivatives of s(t,l) ----
    #pragma unroll
    for (int j = 0; j < J; ++j) {
        const ulonglong2* scv = reinterpret_cast<const ulonglong2*>(&scb[j][0]);
        ulonglong2 v0 = scv[0], v1 = scv[1], v2 = scv[2], v3 = scv[3];
        u64 paX = v0.x, paY = v0.y;          // wl*L2E, bl*L2E
        u64 wtj = v1.x, btj = v1.y;          // wt, bt-0.5
        u64 pbX = v2.x, pbY = v2.y;          // we, we*wt
        u64 pbZ = v3.x, pbW = v3.y;          // we*wl/2, we*wl^2/2

        // --- t-side: sigmoid via degree-6 packed polynomial (no MUFU) ---
        u64 uu  = fma2_(tt2, wtj, btj);      // b - 0.5
        u64 ac  = fma2_(C6, uu, C5);
        ac      = fma2_(ac, uu, C4);
        ac      = fma2_(ac, uu, C3);
        ac      = fma2_(ac, uu, C2);
        ac      = fma2_(ac, uu, C1);
        u64 sg  = fma2_(ac, uu, C0);         // sigmoid(b)
        u64 om  = fma2_(sg, cm1, one2);      // 1 - sg
        u64 sgp = mul2_(sg, om);             // sigmoid'(b)

        // --- l-side ---
        u64 a2  = fma2_(ll2, paX, paY);      // a * log2(e)
        u64 av  = mul2_(a2, ln2_2);          // a
        u64 E   = ex2p(a2);                  // e^a
        u64 E2  = mul2_(E, E);
        u64 q2  = fma2_(E2, e2, one2);       // e*E^2 + 1
        u64 q1  = add2_(E, one2);            // E + 1
        u64 q12 = mul2_(q1, q2);
        u64 R   = rcpp(q12);                 // one rcp for both tanh
        u64 r2v = mul2_(R, q1);              // 1/q2
        u64 r1v = mul2_(R, q2);              // 1/q1
        u64 t1  = fma2_(m2c, r2v, one2);     // tanh(a+0.5)
        u64 nt2 = fma2_(two2, r1v, cm1);     // -tanh(a/2)
        u64 t2  = neg2(nt2);                 // tanh(a/2)      [alu]
        u64 nt1 = neg2(t1);                  //                [alu]
        u64 u1  = fma2_(t1, nt1, one2);      // 1 - t1^2
        u64 u2  = fma2_(t2, nt2, one2);      // 1 - t2^2
        u64 g   = add2_(fma2_(av, t1, c5e4), nt2);        // a*t1 - t2 + 5e-4
        u64 gp  = fma2_(u2, nhalf2, fma2_(av, u1, t1));   // t1 + a*u1 - u2/2
        u64 w   = fma2_(av, nt1, one2);                   // 1 - a*t1
        u64 mm  = mul2_(u1, w);
        u64 ht2 = mul2_(t2, half2);
        u64 gpp = fma2_(ht2, u2, add2_(mm, mm));          // 2*u1*(1-a*t1) + t2*u2/2
        u64 rq  = rsqp(g);
        u64 T   = mul2_(g, rq);              // sqrt(g)
        u64 P1  = mul2_(gp, rq);             // = 2*T'
        u64 hP1 = mul2_(P1, nhalf2);
        u64 x   = fma2_(hP1, P1, gpp);       // gpp - P1^2/2 = 2*(gpp/2 - T'^2)
        u64 P2  = mul2_(x, rq);              // = 2*T''

        s2   = fma2_(pbX, mul2_(T, sg),   s2);
        st2  = fma2_(pbY, mul2_(T, sgp),  st2);
        sl2  = fma2_(pbZ, mul2_(sg, P1),  sl2);   // 1/2 folded into pbZ
        sll2 = fma2_(pbW, mul2_(sg, P2),  sll2);  // 1/2 folded into pbW
    }

    // ---- unpack accumulators ----
    float s[2], st[2], sl[2], sll[2];
    up2(s2,  s[0],  s[1]);
    up2(st2, st[0], st[1]);
    up2(sl2, sl[0], sl[1]);
    up2(sll2,sll[0],sll[1]);

    // ---- PDL: wait for table_kernel completion before touching d_tab ----
    cudaGridDependencySynchronize();

    // ---- Layers via table: nearest-node Taylor of F, F', F'' (L1-cached __ldg) ----
    float2 r0, r1o, r2o, r3o;
    float* p0 = &r0.x; float* p1 = &r1o.x; float* p2 = &r2o.x; float* p3 = &r3o.x;
    #pragma unroll
    for (int n = 0; n < 2; ++n) {
        int i = __float2int_rn(s[n] * TABIH);
        i = min(i, TABN - 1);                // s >= 0 always
        float d = fmaf((float)i, -TABH, s[n]);
        float4 c = __ldg(&d_tab[i]);
        float F2v = fmaf(c.w, d, c.z);
        float F1v = fmaf(fmaf(0.5f * c.w, d, c.z), d, c.y);
        float Fv  = fmaf(fmaf(fmaf(0.16666667f * c.w, d, 0.5f * c.z), d, c.y), d, c.x);
        p0[n] = Fv;
        p1[n] = F1v * st[n];
        p2[n] = F1v * sl[n];
        p3[n] = fmaf(F2v, sl[n] * sl[n], F1v * sll[n]);
    }
    o0[v] = r0;
    o1[v] = r1o;
    o2[v] = r2o;
    o3[v] = r3o;
}

extern "C" void kernel_launch(void* const* d_in, const int* in_sizes, int n_in,
                              void* d_out, int out_size)
{
    const float* ttm  = (const float*)d_in[0];
    const float* logm = (const float*)d_in[1];

    table_kernel<<<TABN/128, 128>>>((const float*)d_in[7],
                                    (const float*)d_in[8],  (const float*)d_in[9],
                                    (const float*)d_in[10], (const float*)d_in[11],
                                    (const float*)d_in[12], (const float*)d_in[13]);

    int B = in_sizes[0];
    int nvec = B >> 1;                 // B = 2^21, divisible by 2
    int blocks = (nvec + 255) / 256;
    float* out = (float*)d_out;

    cudaLaunchConfig_t cfg = {};
    cfg.gridDim  = dim3((unsigned)blocks, 1, 1);
    cfg.blockDim = dim3(256, 1, 1);
    cfg.dynamicSmemBytes = 0;
    cudaLaunchAttribute attrs[1];
    attrs[0].id = cudaLaunchAttributeProgrammaticStreamSerialization;
    attrs[0].val.programmaticStreamSerializationAllowed = 1;
    cfg.attrs = attrs;
    cfg.numAttrs = 1;

    cudaLaunchKernelEx(&cfg, smile_kernel,
                       (const float2*)ttm, (const float2*)logm,
                       (float2*)out,
                       (float2*)(out + (size_t)B),
                       (float2*)(out + 2*(size_t)B),
                       (float2*)(out + 3*(size_t)B),
                       (const float*)d_in[2], (const float*)d_in[3],
                       (const float*)d_in[4], (const float*)d_in[5],
                       (const float*)d_in[6],
                       nvec);
}

// round 15
// speedup vs baseline: 1.0923x; 1.0923x over previous
#include <cuda_runtime.h>

typedef unsigned long long u64;

#define J 5
#define L2E 1.4426950408889634f
#define LN2 0.6931471805599453f
#define E1F 2.7182818284590452f

#define TABN 2048
#define TABH 0.0078125f      // 1/128
#define TABIH 128.0f

// F(s) table: {F, F', F'', F'''} at s = i/128
__device__ float4 d_tab[TABN];

// ---- scalar approx helpers ----
__device__ __forceinline__ float ex2f(float x){ float r; asm("ex2.approx.f32 %0,%1;":"=f"(r):"f"(x)); return r; }
__device__ __forceinline__ float rcpf(float x){ float r; asm("rcp.approx.f32 %0,%1;":"=f"(r):"f"(x)); return r; }
__device__ __forceinline__ float rsqf(float x){ float r; asm("rsqrt.approx.f32 %0,%1;":"=f"(r):"f"(x)); return r; }

// ---- packed f32x2 helpers (sm_103a) ----
__device__ __forceinline__ u64 fma2_(u64 a,u64 b,u64 c){u64 d;asm("fma.rn.f32x2 %0,%1,%2,%3;":"=l"(d):"l"(a),"l"(b),"l"(c));return d;}
__device__ __forceinline__ u64 mul2_(u64 a,u64 b){u64 d;asm("mul.rn.f32x2 %0,%1,%2;":"=l"(d):"l"(a),"l"(b));return d;}
__device__ __forceinline__ u64 add2_(u64 a,u64 b){u64 d;asm("add.rn.f32x2 %0,%1,%2;":"=l"(d):"l"(a),"l"(b));return d;}
__device__ __forceinline__ u64 pk2(float lo,float hi){u64 d;asm("mov.b64 %0,{%1,%2};":"=l"(d):"f"(lo),"f"(hi));return d;}
__device__ __forceinline__ void up2(u64 v,float&lo,float&hi){asm("mov.b64 {%0,%1},%2;":"=f"(lo),"=f"(hi):"l"(v));}
__device__ __forceinline__ u64 bc2(float x){ return pk2(x,x); }
__device__ __forceinline__ u64 ex2p(u64 x){float l,h;up2(x,l,h);return pk2(ex2f(l),ex2f(h));}
__device__ __forceinline__ u64 rcpp(u64 x){float l,h;up2(x,l,h);return pk2(rcpf(l),rcpf(h));}
__device__ __forceinline__ u64 rsqp(u64 x){float l,h;up2(x,l,h);return pk2(rsqf(l),rsqf(h));}
__device__ __forceinline__ u64 neg2(u64 x){ return x ^ 0x8000000080000000ULL; }  // alu pipe

// Build table of F(s) = Wo.softplus(W2.softplus(r1*s + c1) + b2) + bo and
// its first three derivatives wrt the scalar s. One node per thread.
__global__ void table_kernel(const float* __restrict__ bexp,
                             const float* __restrict__ W1, const float* __restrict__ b1,
                             const float* __restrict__ W2, const float* __restrict__ b2,
                             const float* __restrict__ Wo, const float* __restrict__ bo)
{
    cudaTriggerProgrammaticLaunchCompletion();

    int i = blockIdx.x * blockDim.x + threadIdx.x;
    if (i >= TABN) return;
    float s = (float)i * TABH;

    float h1[J], d1[J], dd1[J], ddd1[J];
    #pragma unroll
    for (int j = 0; j < J; ++j) {
        float r = 0.f, c = b1[j];
        #pragma unroll
        for (int k = 0; k < J; ++k) {
            float w = W1[j*J + k];
            r += w;
            c = fmaf(w, bexp[k], c);
        }
        float z   = fmaf(r, s, c);
        float e   = ex2f(-fabsf(z) * L2E);          // exp(-|z|)
        float inv = rcpf(1.f + e);
        float sg  = (z >= 0.f) ? inv : 1.f - inv;   // sigmoid(z)
        float sg1 = sg * (1.f - sg);
        float sg2 = sg1 * (1.f - 2.f * sg);
        h1[j]   = fmaxf(z, 0.f) + __logf(1.f + e);  // softplus(z)
        d1[j]   = sg * r;
        dd1[j]  = sg1 * r * r;
        ddd1[j] = sg2 * r * r * r;
    }

    float F = bo[0], F1 = 0.f, F2 = 0.f, F3 = 0.f;
    #pragma unroll
    for (int j = 0; j < J; ++j) {
        float z2 = b2[j], q = 0.f, m = 0.f, n3 = 0.f;
        #pragma unroll
        for (int k = 0; k < J; ++k) {
            float w = W2[j*J + k];
            z2 = fmaf(w, h1[k], z2);
            q  = fmaf(w, d1[k], q);
            m  = fmaf(w, dd1[k], m);
            n3 = fmaf(w, ddd1[k], n3);
        }
        float e   = ex2f(-fabsf(z2) * L2E);
        float inv = rcpf(1.f + e);
        float sg  = (z2 >= 0.f) ? inv : 1.f - inv;
        float sp  = fmaxf(z2, 0.f) + __logf(1.f + e);
        float sg1 = sg * (1.f - sg);
        float sg2 = sg1 * (1.f - 2.f * sg);
        float wo = Wo[j];
        F  = fmaf(wo, sp, F);
        F1 = fmaf(wo, sg * q, F1);
        F2 = fmaf(wo, fmaf(sg1, q * q, sg * m), F2);
        F3 = fmaf(wo, sg2 * q * q * q + 3.f * sg1 * q * m + sg * n3, F3);
    }
    d_tab[i] = make_float4(F, F1, F2, F3);
}

__global__ __launch_bounds__(256)
void smile_kernel(const float4* __restrict__ ttm4,
                  const float4* __restrict__ logm4,
                  float4* __restrict__ o0, float4* __restrict__ o1,
                  float4* __restrict__ o2, float4* __restrict__ o3,
                  const float* __restrict__ wlogm, const float* __restrict__ blogm,
                  const float* __restrict__ wttm,  const float* __restrict__ bttm,
                  const float* __restrict__ wexp,
                  int nvec)
{
    // Per-block broadcast-packed constants:
    // scb[j] = {wl*L2E, bl*L2E, -wt*L2E, -bt*L2E, we, we*wt, we*wl/2, we*wl^2/2}
    __shared__ __align__(16) u64 scb[J][8];
    if (threadIdx.x < J) {
        int j = threadIdx.x;
        float wl = __expf(wlogm[j]);
        float wt = __expf(wttm[j]);
        float we = __expf(wexp[j]);
        scb[j][0] = bc2(wl * L2E);
        scb[j][1] = bc2(blogm[j] * L2E);
        scb[j][2] = bc2(-wt * L2E);
        scb[j][3] = bc2(-bttm[j] * L2E);
        scb[j][4] = bc2(we);
        scb[j][5] = bc2(we * wt);
        scb[j][6] = bc2(we * wl * 0.5f);        // 1/2 of T' folded here
        scb[j][7] = bc2(we * wl * wl * 0.5f);   // 1/2 of T'' folded here
    }
    __syncthreads();

    int v = blockIdx.x * blockDim.x + threadIdx.x;
    if (v >= nvec) return;

    float4 t4 = ttm4[v];
    float4 l4 = logm4[v];
    u64 tt2[2] = { pk2(t4.x, t4.y), pk2(t4.z, t4.w) };
    u64 ll2[2] = { pk2(l4.x, l4.y), pk2(l4.z, l4.w) };

    const u64 one2   = bc2(1.f);
    const u64 cm1    = bc2(-1.f);
    const u64 two2   = bc2(2.f);
    const u64 m2c    = bc2(-2.f);
    const u64 half2  = bc2(0.5f);
    const u64 nhalf2 = bc2(-0.5f);
    const u64 c5e4   = bc2(5e-4f);
    const u64 e2     = bc2(E1F);
    const u64 ln2_2  = bc2(LN2);

    u64 s2[2]  = {0ull, 0ull};
    u64 st2[2] = {0ull, 0ull};
    u64 sl2[2] = {0ull, 0ull};
    u64 sll2[2]= {0ull, 0ull};

    // ---- Part 1: packed smile/sigmoid terms + derivatives of s(t,l) ----
    // Constants loaded once per j serve BOTH packed pairs (4 samples).
    #pragma unroll
    for (int j = 0; j < J; ++j) {
        u64 paX = scb[j][0], paY = scb[j][1], paZ = scb[j][2], paW = scb[j][3];
        u64 pbX = scb[j][4], pbY = scb[j][5], pbZ = scb[j][6], pbW = scb[j][7];
        #pragma unroll
        for (int p = 0; p < 2; ++p) {
            u64 a2  = fma2_(ll2[p], paX, paY);    // a * log2(e)
            u64 av  = mul2_(a2, ln2_2);           // a
            u64 bm  = fma2_(tt2[p], paZ, paW);    // -b * log2(e)
            u64 E   = ex2p(a2);                   // e^a
            u64 eb  = ex2p(bm);                   // e^{-b}
            u64 E2  = mul2_(E, E);
            u64 q2  = fma2_(E2, e2, one2);        // e*E^2 + 1
            u64 q1  = add2_(E, one2);             // E + 1
            u64 q3  = add2_(eb, one2);            // 1 + e^{-b}
            u64 q12 = mul2_(q1, q2);
            u64 P   = mul2_(q12, q3);
            u64 R   = rcpp(P);                    // one rcp serves all three
            u64 sg  = mul2_(R, q12);              // 1/q3 = sigmoid(b)
            u64 Rq3 = mul2_(R, q3);
            u64 r2v = mul2_(Rq3, q1);             // 1/q2
            u64 r1v = mul2_(Rq3, q2);             // 1/q1
            u64 t1  = fma2_(m2c, r2v, one2);      // tanh(a+0.5)
            u64 nt2 = fma2_(two2, r1v, cm1);      // -tanh(a/2)
            u64 t2  = neg2(nt2);                  // tanh(a/2)      [alu]
            u64 nt1 = neg2(t1);                   //                [alu]
            u64 u1  = fma2_(t1, nt1, one2);       // 1 - t1^2
            u64 u2  = fma2_(t2, nt2, one2);       // 1 - t2^2
            u64 hu2n= mul2_(u2, nhalf2);          // -u2/2 (shared by gp, gpp)
            u64 g   = add2_(fma2_(av, t1, c5e4), nt2);      // a*t1 - t2 + 5e-4
            u64 gp  = add2_(hu2n, fma2_(av, u1, t1));       // t1 + a*u1 - u2/2
            u64 w   = fma2_(av, nt1, one2);                 // 1 - a*t1
            u64 mm  = mul2_(u1, w);
            u64 gpp = fma2_(nt2, hu2n, add2_(mm, mm));      // 2*u1*(1-a*t1) + t2*u2/2
            u64 rq  = rsqp(g);
            u64 T   = mul2_(g, rq);               // sqrt(g)
            u64 P1  = mul2_(gp, rq);              // = 2*T'
            u64 hP1 = mul2_(P1, nhalf2);
            u64 x   = fma2_(hP1, P1, gpp);        // gpp - P1^2/2 = 2*(gpp/2 - T'^2)
            u64 P2  = mul2_(x, rq);               // = 2*T''
            u64 Tsg = mul2_(T, sg);
            u64 seb = mul2_(sg, eb);              // sgp = sg * seb

            s2[p]   = fma2_(pbX, Tsg,             s2[p]);
            st2[p]  = fma2_(pbY, mul2_(Tsg, seb), st2[p]);  // we*wt * T * sg^2 * eb
            sl2[p]  = fma2_(pbZ, mul2_(sg, P1),   sl2[p]);  // 1/2 folded into pbZ
            sll2[p] = fma2_(pbW, mul2_(sg, P2),   sll2[p]); // 1/2 folded into pbW
        }
    }

    // ---- unpack accumulators ----
    float s[4], st[4], sl[4], sll[4];
    up2(s2[0],  s[0],  s[1]);  up2(s2[1],  s[2],  s[3]);
    up2(st2[0], st[0], st[1]); up2(st2[1], st[2], st[3]);
    up2(sl2[0], sl[0], sl[1]); up2(sl2[1], sl[2], sl[3]);
    up2(sll2[0],sll[0],sll[1]);up2(sll2[1],sll[2],sll[3]);

    // ---- PDL: wait for table_kernel completion before touching d_tab ----
    cudaGridDependencySynchronize();

    // ---- Layers via table: nearest-node Taylor of F, F', F'' (L1-cached __ldg) ----
    float4 r0, r1o, r2o, r3o;
    float* p0 = &r0.x; float* p1 = &r1o.x; float* p2 = &r2o.x; float* p3 = &r3o.x;
    #pragma unroll
    for (int n = 0; n < 4; ++n) {
        int i = __float2int_rn(s[n] * TABIH);
        i = min(i, TABN - 1);                    // s >= 0 always
        float d = fmaf((float)i, -TABH, s[n]);
        float4 c = __ldg(&d_tab[i]);
        float F2v = fmaf(c.w, d, c.z);
        float F1v = fmaf(fmaf(0.5f * c.w, d, c.z), d, c.y);
        float Fv  = fmaf(fmaf(fmaf(0.16666667f * c.w, d, 0.5f * c.z), d, c.y), d, c.x);
        p0[n] = Fv;
        p1[n] = F1v * st[n];
        p2[n] = F1v * sl[n];
        p3[n] = fmaf(F2v, sl[n] * sl[n], F1v * sll[n]);
    }
    o0[v] = r0;
    o1[v] = r1o;
    o2[v] = r2o;
    o3[v] = r3o;
}

extern "C" void kernel_launch(void* const* d_in, const int* in_sizes, int n_in,
                              void* d_out, int out_size)
{
    const float* ttm  = (const float*)d_in[0];
    const float* logm = (const float*)d_in[1];

    table_kernel<<<TABN/128, 128>>>((const float*)d_in[7],
                                    (const float*)d_in[8],  (const float*)d_in[9],
                                    (const float*)d_in[10], (const float*)d_in[11],
                                    (const float*)d_in[12], (const float*)d_in[13]);

    int B = in_sizes[0];
    int nvec = B >> 2;                 // B = 2^21, divisible by 4
    int blocks = (nvec + 255) / 256;
    float* out = (float*)d_out;

    cudaLaunchConfig_t cfg = {};
    cfg.gridDim  = dim3((unsigned)blocks, 1, 1);
    cfg.blockDim = dim3(256, 1, 1);
    cfg.dynamicSmemBytes = 0;
    cudaLaunchAttribute attrs[1];
    attrs[0].id = cudaLaunchAttributeProgrammaticStreamSerialization;
    attrs[0].val.programmaticStreamSerializationAllowed = 1;
    cfg.attrs = attrs;
    cfg.numAttrs = 1;

    cudaLaunchKernelEx(&cfg, smile_kernel,
                       (const float4*)ttm, (const float4*)logm,
                       (float4*)out,
                       (float4*)(out + (size_t)B),
                       (float4*)(out + 2*(size_t)B),
                       (float4*)(out + 3*(size_t)B),
                       (const float*)d_in[2], (const float*)d_in[3],
                       (const float*)d_in[4], (const float*)d_in[5],
                       (const float*)d_in[6],
                       nvec);
}